// round 4
// baseline (speedup 1.0000x reference)
#include <cuda_runtime.h>
#include <cuda_fp16.h>
#include <math.h>
#include <math_constants.h>

#define NN 100000
#define F1 128
#define H1 4
#define OUTC 10
#define OP 16
#define NG 128
#define EMAX 1600000
#define NEG_SLOPE 0.2f

// ---------------- scratch ----------------
__device__ __align__(16) __half g_h1h[NN * F1];   // layer1 features fp16
__device__ __align__(16) float  g_as1[NN * H1];
__device__ __align__(16) float  g_ad1[NN * H1];

__device__ __align__(16) __half g_h2ph[NN * OP];  // layer2 features (padded 16)
__device__ float g_as2[NN];
__device__ float g_ad2[NN];

__device__ int g_deg[NN];
__device__ int g_off[NN + 1];
__device__ int g_cur[NN];
__device__ int g_srcl[EMAX];

__device__ float g_pool[NG * OUTC];

// ---------------- helpers ----------------
__device__ __forceinline__ float lrelu(float v) { return v > 0.0f ? v : NEG_SLOPE * v; }
__device__ __forceinline__ float elu(float v)   { return v > 0.0f ? v : expm1f(v); }

__device__ __forceinline__ unsigned long long pack2(float lo, float hi) {
    unsigned long long r;
    asm("mov.b64 %0, {%1, %2};" : "=l"(r) : "f"(lo), "f"(hi));
    return r;
}
__device__ __forceinline__ void unpack2(float& lo, float& hi, unsigned long long v) {
    asm("mov.b64 {%0, %1}, %2;" : "=f"(lo), "=f"(hi) : "l"(v));
}
__device__ __forceinline__ void fma2(unsigned long long& d, unsigned long long a, unsigned long long b) {
    asm("fma.rn.f32x2 %0, %1, %2, %0;" : "+l"(d) : "l"(a), "l"(b));
}

// ---------------- GEMM1 + fused attention dots ----------------
#define TM 64
__global__ void gemm1_att_kernel(const float* __restrict__ x, const float* __restrict__ W1,
                                 const float* __restrict__ att_s, const float* __restrict__ att_d) {
    extern __shared__ float smem[];
    float* Ws = smem;               // 128*128
    float* xs = smem + F1 * F1;     // 64*132
    float4* Wsv = (float4*)Ws;
    int t = threadIdx.x;            // 256 threads
    const float4* W1v = (const float4*)W1;
    for (int i = t; i < F1 * F1 / 4; i += 256) Wsv[i] = W1v[i];
    int row0 = blockIdx.x * TM;
    const float4* xv = (const float4*)x;
    for (int i = t; i < TM * 32; i += 256) {
        int r = i >> 5, c4 = i & 31;
        int gr = row0 + r;
        float4 v = (gr < NN) ? xv[gr * 32 + c4] : make_float4(0, 0, 0, 0);
        *(float4*)&xs[r * 132 + c4 * 4] = v;
    }
    __syncthreads();
    int tx = t & 31, ty = t >> 5;
    unsigned long long acc[8][2];
#pragma unroll
    for (int r = 0; r < 8; r++) { acc[r][0] = 0ULL; acc[r][1] = 0ULL; }

#pragma unroll 4
    for (int k = 0; k < F1; k++) {
        float4 w = Wsv[k * 32 + tx];
        unsigned long long w01 = pack2(w.x, w.y);
        unsigned long long w23 = pack2(w.z, w.w);
#pragma unroll
        for (int r = 0; r < 8; r++) {
            float xk = xs[(ty * 8 + r) * 132 + k];
            unsigned long long x2 = pack2(xk, xk);
            fma2(acc[r][0], x2, w01);
            fma2(acc[r][1], x2, w23);
        }
    }

    float4 as4 = ((const float4*)att_s)[tx];
    float4 ad4 = ((const float4*)att_d)[tx];
#pragma unroll
    for (int r = 0; r < 8; r++) {
        int gr = row0 + ty * 8 + r;
        float a0, a1, a2, a3;
        unpack2(a0, a1, acc[r][0]);
        unpack2(a2, a3, acc[r][1]);
        if (gr < NN) {
            __half2 p0 = __floats2half2_rn(a0, a1);
            __half2 p1 = __floats2half2_rn(a2, a3);
            __half2* hp = (__half2*)&g_h1h[gr * F1 + tx * 4];
            hp[0] = p0; hp[1] = p1;
        }
        float sp = a0 * as4.x + a1 * as4.y + a2 * as4.z + a3 * as4.w;
        float dp = a0 * ad4.x + a1 * ad4.y + a2 * ad4.z + a3 * ad4.w;
#pragma unroll
        for (int o = 1; o < 8; o <<= 1) {
            sp += __shfl_xor_sync(0xffffffffu, sp, o);
            dp += __shfl_xor_sync(0xffffffffu, dp, o);
        }
        if ((tx & 7) == 0 && gr < NN) {
            g_as1[gr * H1 + (tx >> 3)] = sp;
            g_ad1[gr * H1 + (tx >> 3)] = dp;
        }
    }
}

// ---------------- CSR build ----------------
__global__ void hist_kernel(const int* __restrict__ ei, int E_real) {
    int e = blockIdx.x * blockDim.x + threadIdx.x;
    if (e < E_real) atomicAdd(&g_deg[ei[E_real + e]], 1);
}

__global__ void prefix_kernel() {
    __shared__ int ssum[1024];
    int t = threadIdx.x;
    const int CH = (NN + 1023) / 1024;
    int base = t * CH;
    int sum = 0;
    for (int i = 0; i < CH; i++) {
        int idx = base + i;
        if (idx < NN) sum += g_deg[idx];
    }
    ssum[t] = sum;
    __syncthreads();
    for (int o = 1; o < 1024; o <<= 1) {
        int v = (t >= o) ? ssum[t - o] : 0;
        __syncthreads();
        ssum[t] += v;
        __syncthreads();
    }
    int running = ssum[t] - sum;   // exclusive prefix
    for (int i = 0; i < CH; i++) {
        int idx = base + i;
        if (idx < NN) {
            g_off[idx] = running;
            g_cur[idx] = running;
            running += g_deg[idx];
        }
    }
    if (t == 1023) g_off[NN] = ssum[1023];
}

__global__ void scatter_kernel(const int* __restrict__ ei, int E_real) {
    int e = blockIdx.x * blockDim.x + threadIdx.x;
    if (e >= E_real) return;
    int d = ei[E_real + e];
    int pos = atomicAdd(&g_cur[d], 1);
    g_srcl[pos] = ei[e];
}

// ---------------- layer1 pull-aggregate fused with layer2 node compute ----------------
__global__ void agg1_kernel(const float* __restrict__ W2,
                            const float* __restrict__ att_s2,
                            const float* __restrict__ att_d2,
                            const float* __restrict__ b1) {
    __shared__ float W2t[OUTC * F1];     // transposed: [c][ch]
    __shared__ float s_as[OUTC], s_ad[OUTC];
    int t = threadIdx.x;
    for (int i = t; i < OUTC * F1; i += 256) {
        int c = i >> 7, ch = i & 127;
        W2t[i] = W2[ch * OUTC + c];
    }
    if (t < OUTC) { s_as[t] = att_s2[t]; s_ad[t] = att_d2[t]; }
    __syncthreads();

    int node = (blockIdx.x * 256 + t) >> 5;
    int lane = t & 31;
    if (node >= NN) return;
    int head = lane >> 3;

    float4 ad4 = *(const float4*)&g_ad1[node * H1];
    float a_d = (head & 2) ? ((head & 1) ? ad4.w : ad4.z)
                           : ((head & 1) ? ad4.y : ad4.x);
    // self loop
    float4 asS = *(const float4*)&g_as1[node * H1];
    float a_sS = (head & 2) ? ((head & 1) ? asS.w : asS.z)
                            : ((head & 1) ? asS.y : asS.x);
    float ex = __expf(lrelu(a_sS + a_d));
    float den = ex;
    uint2 hv = *(const uint2*)&g_h1h[node * F1 + lane * 4];
    float2 f0 = __half22float2(*(__half2*)&hv.x);
    float2 f1 = __half22float2(*(__half2*)&hv.y);
    float ac0 = ex * f0.x, ac1 = ex * f0.y, ac2 = ex * f1.x, ac3 = ex * f1.y;

    int start = g_off[node], end = g_off[node + 1];
#pragma unroll 2
    for (int i = start; i < end; i++) {
        int s = __ldg(&g_srcl[i]);
        float4 as4 = __ldg((const float4*)&g_as1[s * H1]);
        float a_s = (head & 2) ? ((head & 1) ? as4.w : as4.z)
                               : ((head & 1) ? as4.y : as4.x);
        float e2 = __expf(lrelu(a_s + a_d));
        den += e2;
        uint2 h2 = __ldg((const uint2*)&g_h1h[s * F1 + lane * 4]);
        float2 g0 = __half22float2(*(__half2*)&h2.x);
        float2 g1 = __half22float2(*(__half2*)&h2.y);
        ac0 += e2 * g0.x; ac1 += e2 * g0.y;
        ac2 += e2 * g1.x; ac3 += e2 * g1.y;
    }

    float inv = 1.0f / (den + 1e-16f);
    float4 b4 = __ldg((const float4*)&b1[lane * 4]);
    float h0 = elu(ac0 * inv + b4.x);
    float h1 = elu(ac1 * inv + b4.y);
    float h2 = elu(ac2 * inv + b4.z);
    float h3 = elu(ac3 * inv + b4.w);

    float part[OUTC];
#pragma unroll
    for (int c = 0; c < OUTC; c++) {
        float4 w = *(const float4*)&W2t[c * F1 + lane * 4];
        part[c] = h0 * w.x + h1 * w.y + h2 * w.z + h3 * w.w;
    }
#pragma unroll
    for (int o = 16; o; o >>= 1)
#pragma unroll
        for (int c = 0; c < OUTC; c++)
            part[c] += __shfl_xor_sync(0xffffffffu, part[c], o);

    if (lane == 0) {
        __half2 p01 = __floats2half2_rn(part[0], part[1]);
        __half2 p23 = __floats2half2_rn(part[2], part[3]);
        __half2 p45 = __floats2half2_rn(part[4], part[5]);
        __half2 p67 = __floats2half2_rn(part[6], part[7]);
        __half2 p89 = __floats2half2_rn(part[8], part[9]);
        uint4 v0, v1;
        v0.x = *(unsigned*)&p01; v0.y = *(unsigned*)&p23;
        v0.z = *(unsigned*)&p45; v0.w = *(unsigned*)&p67;
        v1.x = *(unsigned*)&p89; v1.y = 0u; v1.z = 0u; v1.w = 0u;
        *(uint4*)&g_h2ph[node * OP]     = v0;
        *(uint4*)&g_h2ph[node * OP + 8] = v1;
        float as = 0.0f, ad = 0.0f;
#pragma unroll
        for (int c = 0; c < OUTC; c++) { as += part[c] * s_as[c]; ad += part[c] * s_ad[c]; }
        g_as2[node] = as;
        g_ad2[node] = ad;
    }
}

// ---------------- layer2 pull-aggregate + pooling ----------------
__global__ void agg2pool_kernel(const float* __restrict__ b2, const int* __restrict__ batch) {
    int n = blockIdx.x * blockDim.x + threadIdx.x;
    if (n >= NN) return;
    float a_d = g_ad2[n];
    float ex = __expf(lrelu(g_as2[n] + a_d));
    float den = ex;
    float acc[OUTC];
    {
        uint4 v0 = *(const uint4*)&g_h2ph[n * OP];
        uint  v8 = *(const unsigned*)&g_h2ph[n * OP + 8];
        float2 f;
        f = __half22float2(*(__half2*)&v0.x); acc[0] = ex * f.x; acc[1] = ex * f.y;
        f = __half22float2(*(__half2*)&v0.y); acc[2] = ex * f.x; acc[3] = ex * f.y;
        f = __half22float2(*(__half2*)&v0.z); acc[4] = ex * f.x; acc[5] = ex * f.y;
        f = __half22float2(*(__half2*)&v0.w); acc[6] = ex * f.x; acc[7] = ex * f.y;
        f = __half22float2(*(__half2*)&v8);   acc[8] = ex * f.x; acc[9] = ex * f.y;
    }
    int start = g_off[n], end = g_off[n + 1];
#pragma unroll 2
    for (int i = start; i < end; i++) {
        int s = __ldg(&g_srcl[i]);
        float e2 = __expf(lrelu(__ldg(&g_as2[s]) + a_d));
        den += e2;
        uint4 w0 = __ldg((const uint4*)&g_h2ph[s * OP]);
        uint  w8 = __ldg((const unsigned*)&g_h2ph[s * OP + 8]);
        float2 f;
        f = __half22float2(*(__half2*)&w0.x); acc[0] += e2 * f.x; acc[1] += e2 * f.y;
        f = __half22float2(*(__half2*)&w0.y); acc[2] += e2 * f.x; acc[3] += e2 * f.y;
        f = __half22float2(*(__half2*)&w0.z); acc[4] += e2 * f.x; acc[5] += e2 * f.y;
        f = __half22float2(*(__half2*)&w0.w); acc[6] += e2 * f.x; acc[7] += e2 * f.y;
        f = __half22float2(*(__half2*)&w8);   acc[8] += e2 * f.x; acc[9] += e2 * f.y;
    }
    float inv = 1.0f / (den + 1e-16f);
    int g = batch[n];
#pragma unroll
    for (int c = 0; c < OUTC; c++)
        atomicAdd(&g_pool[g * OUTC + c], elu(acc[c] * inv + __ldg(&b2[c])));
}

// ---------------- final: mean (counts via binary search) + log_softmax ----------------
__global__ void final_kernel(const int* __restrict__ batch, float* __restrict__ out) {
    int g = threadIdx.x;
    if (g >= NG) return;
    int lo = 0, hi = NN;
    while (lo < hi) { int mid = (lo + hi) >> 1; if (batch[mid] < g) lo = mid + 1; else hi = mid; }
    int lb = lo;
    lo = 0; hi = NN;
    while (lo < hi) { int mid = (lo + hi) >> 1; if (batch[mid] <= g) lo = mid + 1; else hi = mid; }
    float cnt = fmaxf((float)(lo - lb), 1.0f);
    float p[OUTC];
    float mx = -CUDART_INF_F;
#pragma unroll
    for (int c = 0; c < OUTC; c++) {
        p[c] = g_pool[g * OUTC + c] / cnt;
        mx = fmaxf(mx, p[c]);
    }
    float se = 0.0f;
#pragma unroll
    for (int c = 0; c < OUTC; c++) se += expf(p[c] - mx);
    float lse = mx + logf(se);
#pragma unroll
    for (int c = 0; c < OUTC; c++) out[g * OUTC + c] = p[c] - lse;
}

// ---------------- launch ----------------
extern "C" void kernel_launch(void* const* d_in, const int* in_sizes, int n_in,
                              void* d_out, int out_size) {
    const float* x      = (const float*)d_in[0];
    const float* W1     = (const float*)d_in[1];
    const float* att_s1 = (const float*)d_in[2];
    const float* att_d1 = (const float*)d_in[3];
    const float* b1     = (const float*)d_in[4];
    const float* W2     = (const float*)d_in[5];
    const float* att_s2 = (const float*)d_in[6];
    const float* att_d2 = (const float*)d_in[7];
    const float* b2     = (const float*)d_in[8];
    const int*   ei     = (const int*)d_in[9];
    const int*   batch  = (const int*)d_in[10];
    float* out = (float*)d_out;

    int E_real = in_sizes[9] / 2;

    void *p_deg, *p_pool;
    cudaGetSymbolAddress(&p_deg,  g_deg);
    cudaGetSymbolAddress(&p_pool, g_pool);
    cudaMemsetAsync(p_deg,  0, (size_t)NN * sizeof(int));
    cudaMemsetAsync(p_pool, 0, (size_t)NG * OUTC * sizeof(float));

    // CSR build
    hist_kernel<<<(E_real + 255) / 256, 256>>>(ei, E_real);
    prefix_kernel<<<1, 1024>>>();
    scatter_kernel<<<(E_real + 255) / 256, 256>>>(ei, E_real);

    // GEMM1 + attention dots
    int gemm1_smem = (F1 * F1 + TM * 132) * (int)sizeof(float);
    cudaFuncSetAttribute(gemm1_att_kernel, cudaFuncAttributeMaxDynamicSharedMemorySize, gemm1_smem);
    gemm1_att_kernel<<<(NN + TM - 1) / TM, 256, gemm1_smem>>>(x, W1, att_s1, att_d1);

    // layer1 aggregate + layer2 node compute (warp per node)
    agg1_kernel<<<(NN * 32 + 255) / 256, 256>>>(W2, att_s2, att_d2, b1);

    // layer2 aggregate + pooling (thread per node)
    agg2pool_kernel<<<(NN + 255) / 256, 256>>>(b2, batch);

    final_kernel<<<1, NG>>>(batch, out);
}

// round 5
// speedup vs baseline: 1.3264x; 1.3264x over previous
#include <cuda_runtime.h>
#include <cuda_fp16.h>
#include <math.h>
#include <math_constants.h>

#define NN 100000
#define F1 128
#define H1 4
#define OUTC 10
#define OP 16
#define NG 128
#define NEG_SLOPE 0.2f

#define XS 136   // padded smem stride (halves)
#define WS 136

// ---------------- scratch ----------------
__device__ __align__(16) __half g_h1h[NN * F1];    // layer1 features, fp16
__device__ __align__(16) __half g_acc1h[NN * F1];  // fp16 atomic accumulator
__device__ __align__(16) float  g_as1[NN * H1];
__device__ __align__(16) float  g_ad1[NN * H1];
__device__ __align__(16) float  g_den1[NN * H1];

__device__ __align__(16) __half g_W1h[F1 * F1];    // W1 transposed [n][k], fp16

__device__ __align__(16) __half g_h2ph[NN * OP];
__device__ __align__(16) __half g_acc2ph[NN * OP];
__device__ float g_as2[NN];
__device__ float g_ad2[NN];
__device__ float g_den2[NN];

__device__ float g_pool[NG * OUTC];
__device__ float g_cnt[NG];

// ---------------- helpers ----------------
__device__ __forceinline__ float lrelu(float v) { return v > 0.0f ? v : NEG_SLOPE * v; }
__device__ __forceinline__ float elu(float v)   { return v > 0.0f ? v : expm1f(v); }

__device__ __forceinline__ void mma16816(float c[4],
                                         unsigned a0, unsigned a1, unsigned a2, unsigned a3,
                                         unsigned b0, unsigned b1) {
    asm volatile("mma.sync.aligned.m16n8k16.row.col.f32.f16.f16.f32 "
                 "{%0,%1,%2,%3}, {%4,%5,%6,%7}, {%8,%9}, {%0,%1,%2,%3};"
                 : "+f"(c[0]), "+f"(c[1]), "+f"(c[2]), "+f"(c[3])
                 : "r"(a0), "r"(a1), "r"(a2), "r"(a3), "r"(b0), "r"(b1));
}

// ---------------- W1 convert + transpose: g_W1h[n*128+k] = (half)W1[k*128+n] ----------------
__global__ void convert_w_kernel(const float* __restrict__ W1) {
    int t = blockIdx.x * blockDim.x + threadIdx.x;
    if (t >= F1 * F1) return;
    int n = t >> 7, k = t & 127;
    g_W1h[t] = __float2half(W1[k * F1 + n]);
}

// ---------------- GEMM1 (tensor core) + fused attention dots ----------------
// block: 256 threads, 64 rows x 128 cols; 8 warps as 4(m16) x 2(n64)
__global__ void gemm1_att_kernel(const float* __restrict__ x,
                                 const float* __restrict__ att_s,
                                 const float* __restrict__ att_d) {
    extern __shared__ __half smem[];
    __half* Wt = smem;                    // [128][WS]
    __half* xs = smem + F1 * WS;          // [64][XS], later reused as output staging
    float* satt = (float*)(xs + 64 * XS); // [256]: att_s | att_d

    int t = threadIdx.x;
    int row0 = blockIdx.x * 64;

    // load Wt (fp16, already [n][k]) into padded smem, 8 halves per uint4
    const uint4* wsrc = (const uint4*)g_W1h;
    for (int i = t; i < F1 * F1 / 8; i += 256) {
        int n = i >> 4, kc = (i & 15) * 8;
        *(uint4*)&Wt[n * WS + kc] = wsrc[i];
    }
    // load + convert x tile (64 x 128 fp32 -> fp16)
    const float4* xv = (const float4*)x;
    for (int i = t; i < 64 * 32; i += 256) {
        int r = i >> 5, c4 = i & 31;
        int gr = row0 + r;
        float4 v = (gr < NN) ? xv[gr * 32 + c4] : make_float4(0, 0, 0, 0);
        __half2 h0 = __floats2half2_rn(v.x, v.y);
        __half2 h1 = __floats2half2_rn(v.z, v.w);
        *(__half2*)&xs[r * XS + c4 * 4]     = h0;
        *(__half2*)&xs[r * XS + c4 * 4 + 2] = h1;
    }
    if (t < 128) { satt[t] = att_s[t]; satt[128 + t] = att_d[t]; }
    __syncthreads();

    int wid = t >> 5, lane = t & 31;
    int wm = wid & 3, wn = wid >> 2;
    int rq = lane >> 2;          // 0..7
    int q2 = (lane & 3) * 2;     // 0,2,4,6
    int rA = wm * 16 + rq;

    float c[8][4];
#pragma unroll
    for (int nt = 0; nt < 8; nt++)
#pragma unroll
        for (int j = 0; j < 4; j++) c[nt][j] = 0.0f;

#pragma unroll
    for (int kb = 0; kb < F1; kb += 16) {
        unsigned a0 = *(unsigned*)&xs[rA * XS + kb + q2];
        unsigned a1 = *(unsigned*)&xs[(rA + 8) * XS + kb + q2];
        unsigned a2 = *(unsigned*)&xs[rA * XS + kb + q2 + 8];
        unsigned a3 = *(unsigned*)&xs[(rA + 8) * XS + kb + q2 + 8];
#pragma unroll
        for (int nt = 0; nt < 8; nt++) {
            int n = wn * 64 + nt * 8 + rq;
            unsigned b0 = *(unsigned*)&Wt[n * WS + kb + q2];
            unsigned b1 = *(unsigned*)&Wt[n * WS + kb + q2 + 8];
            mma16816(c[nt], a0, a1, a2, a3, b0, b1);
        }
    }

    __syncthreads();   // x reads done; reuse xs as output staging
    __half* es = xs;   // [64][XS]
#pragma unroll
    for (int nt = 0; nt < 8; nt++) {
        int col = wn * 64 + nt * 8 + q2;
        *(__half2*)&es[rA * XS + col]       = __floats2half2_rn(c[nt][0], c[nt][1]);
        *(__half2*)&es[(rA + 8) * XS + col] = __floats2half2_rn(c[nt][2], c[nt][3]);
    }
    __syncthreads();

    // attention dots: thread = (row = t>>2, head = t&3)
    {
        int row = t >> 2, head = t & 3;
        int grow = row0 + row;
        if (grow < NN) {
            float s = 0.0f, d = 0.0f;
#pragma unroll
            for (int i = 0; i < 16; i++) {
                float2 f = __half22float2(*(__half2*)&es[row * XS + head * 32 + i * 2]);
                s += f.x * satt[head * 32 + i * 2] + f.y * satt[head * 32 + i * 2 + 1];
                d += f.x * satt[128 + head * 32 + i * 2] + f.y * satt[128 + head * 32 + i * 2 + 1];
            }
            g_as1[grow * H1 + head] = s;
            g_ad1[grow * H1 + head] = d;
        }
    }
    // coalesced fp16 h1 store: 1024 uint4
#pragma unroll
    for (int j = 0; j < 4; j++) {
        int idx = t * 4 + j;            // 0..1023
        int r2 = idx >> 4, c8 = (idx & 15) * 8;
        int gr = row0 + r2;
        if (gr < NN)
            *(uint4*)&g_h1h[gr * F1 + c8] = *(uint4*)&es[r2 * XS + c8];
    }
}

// ---------------- edge accumulate layer1: 16 lanes per edge, fp16 ----------------
__global__ void edge_acc1_kernel(const int* __restrict__ ei, int E_real, int E_tot) {
    int gtid = blockIdx.x * blockDim.x + threadIdx.x;
    int e = gtid >> 4;
    int sl = threadIdx.x & 15;
    int wl = threadIdx.x & 31;
    if (e >= E_tot) return;
    int s, d;
    if (e < E_real) { s = __ldg(&ei[e]); d = __ldg(&ei[E_real + e]); }
    else            { s = d = e - E_real; }
    float ex = 0.0f;
    if (sl < H1) {
        float v = lrelu(g_as1[s * H1 + sl] + g_ad1[d * H1 + sl]);
        ex = __expf(v);
        atomicAdd(&g_den1[d * H1 + sl], ex);
    }
    float exl = __shfl_sync(0xffffffffu, ex, (wl & 16) + (sl >> 2));
    __half2 ex2 = __float2half2_rn(exl);
    uint4 raw = *(const uint4*)&g_h1h[s * F1 + sl * 8];
    __half2 m0 = __hmul2(*(__half2*)&raw.x, ex2);
    __half2 m1 = __hmul2(*(__half2*)&raw.y, ex2);
    __half2 m2 = __hmul2(*(__half2*)&raw.z, ex2);
    __half2 m3 = __hmul2(*(__half2*)&raw.w, ex2);
    __half* dst = &g_acc1h[d * F1 + sl * 8];
    asm volatile("red.global.add.noftz.v4.f16x2 [%0], {%1,%2,%3,%4};"
                 :: "l"(dst), "r"(*(unsigned*)&m0), "r"(*(unsigned*)&m1),
                    "r"(*(unsigned*)&m2), "r"(*(unsigned*)&m3) : "memory");
}

// ---------------- layer2 node kernel ----------------
__global__ void layer2_node_kernel(const float* __restrict__ W2,
                                   const float* __restrict__ att_s2,
                                   const float* __restrict__ att_d2,
                                   const float* __restrict__ b1) {
    __shared__ float W2s[F1 * 11];
    __shared__ float s_as[OUTC], s_ad[OUTC];
    int t = threadIdx.x;
    for (int i = t; i < F1 * OUTC; i += 256) W2s[(i / OUTC) * 11 + (i % OUTC)] = W2[i];
    if (t < OUTC) { s_as[t] = att_s2[t]; s_ad[t] = att_d2[t]; }
    __syncthreads();
    int node = (blockIdx.x * 256 + t) >> 5;
    int lane = t & 31;
    if (node >= NN) return;
    float4 den4 = *(const float4*)&g_den1[node * H1];
    float inv[4] = { 1.0f / (den4.x + 1e-16f), 1.0f / (den4.y + 1e-16f),
                     1.0f / (den4.z + 1e-16f), 1.0f / (den4.w + 1e-16f) };
    float out[OUTC];
#pragma unroll
    for (int c = 0; c < OUTC; c++) out[c] = 0.0f;
#pragma unroll
    for (int i = 0; i < 4; i++) {
        int ch = lane + 32 * i;
        float a = __half2float(g_acc1h[node * F1 + ch]);
        float h = elu(a * inv[i] + __ldg(&b1[ch]));
        const float* wr = &W2s[ch * 11];
#pragma unroll
        for (int c = 0; c < OUTC; c++) out[c] += h * wr[c];
    }
#pragma unroll
    for (int o = 16; o; o >>= 1)
#pragma unroll
        for (int c = 0; c < OUTC; c++) out[c] += __shfl_xor_sync(0xffffffffu, out[c], o);
    if (lane < 8) {
        float lo = 0.0f, hi = 0.0f;
        if (lane < 5) { lo = out[2 * lane]; hi = out[2 * lane + 1]; }
        ((__half2*)&g_h2ph[node * OP])[lane] = __floats2half2_rn(lo, hi);
    }
    if (lane == 0) {
        float as = 0.0f, ad = 0.0f;
#pragma unroll
        for (int c = 0; c < OUTC; c++) { as += out[c] * s_as[c]; ad += out[c] * s_ad[c]; }
        g_as2[node] = as;
        g_ad2[node] = ad;
    }
}

// ---------------- edge accumulate layer2: 4 lanes per edge, fp16 ----------------
__global__ void edge_acc2_kernel(const int* __restrict__ ei, int E_real, int E_tot) {
    int gtid = blockIdx.x * blockDim.x + threadIdx.x;
    int e = gtid >> 2;
    int li = threadIdx.x & 3;
    int wl = threadIdx.x & 31;
    if (e >= E_tot) return;
    int s, d;
    if (e < E_real) { s = __ldg(&ei[e]); d = __ldg(&ei[E_real + e]); }
    else            { s = d = e - E_real; }
    float ex = 0.0f;
    if (li == 0) {
        float v = lrelu(g_as2[s] + g_ad2[d]);
        ex = __expf(v);
        atomicAdd(&g_den2[d], ex);
    }
    float exl = __shfl_sync(0xffffffffu, ex, wl & ~3);
    __half2 ex2 = __float2half2_rn(exl);
    uint2 raw = *(const uint2*)&g_h2ph[s * OP + li * 4];
    __half2 m0 = __hmul2(*(__half2*)&raw.x, ex2);
    __half2 m1 = __hmul2(*(__half2*)&raw.y, ex2);
    __half* dst = &g_acc2ph[d * OP + li * 4];
    asm volatile("red.global.add.noftz.v2.f16x2 [%0], {%1,%2};"
                 :: "l"(dst), "r"(*(unsigned*)&m0), "r"(*(unsigned*)&m1) : "memory");
}

// ---------------- finalize layer2 + pooling ----------------
__global__ void fin2pool_kernel(const float* __restrict__ b2, const int* __restrict__ batch) {
    int n = blockIdx.x * blockDim.x + threadIdx.x;
    if (n >= NN) return;
    float inv = 1.0f / (g_den2[n] + 1e-16f);
    int g = batch[n];
#pragma unroll
    for (int c = 0; c < OUTC; c++) {
        float v = elu(__half2float(g_acc2ph[n * OP + c]) * inv + b2[c]);
        atomicAdd(&g_pool[g * OUTC + c], v);
    }
    atomicAdd(&g_cnt[g], 1.0f);
}

// ---------------- final: mean + log_softmax ----------------
__global__ void final_kernel(float* __restrict__ out) {
    int g = threadIdx.x;
    if (g >= NG) return;
    float cnt = fmaxf(g_cnt[g], 1.0f);
    float p[OUTC];
    float mx = -CUDART_INF_F;
#pragma unroll
    for (int c = 0; c < OUTC; c++) {
        p[c] = g_pool[g * OUTC + c] / cnt;
        mx = fmaxf(mx, p[c]);
    }
    float se = 0.0f;
#pragma unroll
    for (int c = 0; c < OUTC; c++) se += expf(p[c] - mx);
    float lse = mx + logf(se);
#pragma unroll
    for (int c = 0; c < OUTC; c++) out[g * OUTC + c] = p[c] - lse;
}

// ---------------- launch ----------------
extern "C" void kernel_launch(void* const* d_in, const int* in_sizes, int n_in,
                              void* d_out, int out_size) {
    const float* x      = (const float*)d_in[0];
    const float* W1     = (const float*)d_in[1];
    const float* att_s1 = (const float*)d_in[2];
    const float* att_d1 = (const float*)d_in[3];
    const float* b1     = (const float*)d_in[4];
    const float* W2     = (const float*)d_in[5];
    const float* att_s2 = (const float*)d_in[6];
    const float* att_d2 = (const float*)d_in[7];
    const float* b2     = (const float*)d_in[8];
    const int*   ei     = (const int*)d_in[9];
    const int*   batch  = (const int*)d_in[10];
    float* out = (float*)d_out;

    int E_real = in_sizes[9] / 2;
    int E_tot = E_real + NN;

    void *p_acc1, *p_den1, *p_acc2, *p_den2, *p_pool, *p_cnt;
    cudaGetSymbolAddress(&p_acc1, g_acc1h);
    cudaGetSymbolAddress(&p_den1, g_den1);
    cudaGetSymbolAddress(&p_acc2, g_acc2ph);
    cudaGetSymbolAddress(&p_den2, g_den2);
    cudaGetSymbolAddress(&p_pool, g_pool);
    cudaGetSymbolAddress(&p_cnt,  g_cnt);

    cudaMemsetAsync(p_acc1, 0, (size_t)NN * F1 * sizeof(__half));
    cudaMemsetAsync(p_den1, 0, (size_t)NN * H1 * sizeof(float));
    cudaMemsetAsync(p_acc2, 0, (size_t)NN * OP * sizeof(__half));
    cudaMemsetAsync(p_den2, 0, (size_t)NN * sizeof(float));
    cudaMemsetAsync(p_pool, 0, (size_t)NG * OUTC * sizeof(float));
    cudaMemsetAsync(p_cnt,  0, (size_t)NG * sizeof(float));

    convert_w_kernel<<<(F1 * F1 + 255) / 256, 256>>>(W1);

    int gemm_smem = (F1 * WS + 64 * XS) * (int)sizeof(__half) + 256 * (int)sizeof(float);
    cudaFuncSetAttribute(gemm1_att_kernel, cudaFuncAttributeMaxDynamicSharedMemorySize, gemm_smem);
    gemm1_att_kernel<<<(NN + 63) / 64, 256, gemm_smem>>>(x, att_s1, att_d1);

    long long th1 = (long long)E_tot * 16;
    edge_acc1_kernel<<<(int)((th1 + 255) / 256), 256>>>(ei, E_real, E_tot);

    layer2_node_kernel<<<(NN * 32 + 255) / 256, 256>>>(W2, att_s2, att_d2, b1);

    long long th2 = (long long)E_tot * 4;
    edge_acc2_kernel<<<(int)((th2 + 255) / 256), 256>>>(ei, E_real, E_tot);

    fin2pool_kernel<<<(NN + 255) / 256, 256>>>(b2, batch);

    final_kernel<<<1, NG>>>(out);
}

// round 6
// speedup vs baseline: 1.4656x; 1.1050x over previous
#include <cuda_runtime.h>
#include <cuda_fp16.h>
#include <math.h>
#include <math_constants.h>

#define NN 100000
#define F1 128
#define H1 4
#define OUTC 10
#define OP 16
#define NG 128
#define NEG_SLOPE 0.2f

#define XS 136   // padded smem stride (halves)
#define WS 136

// ---------------- scratch ----------------
__device__ __align__(16) __half g_h1h[NN * F1];    // layer1 features, fp16
__device__ __align__(16) __half g_acc1h[NN * F1];  // fp16 atomic accumulator
__device__ __align__(16) float  g_as1[NN * H1];
__device__ __align__(16) float  g_ad1[NN * H1];
__device__ __align__(16) float  g_den1[NN * H1];

__device__ __align__(16) __half g_W1h[F1 * F1];    // W1 transposed [n][k], fp16
__device__ __align__(16) __half g_W2h[OP * F1];    // W2 transposed [n][k] (padded to 16), fp16

__device__ __align__(16) __half g_h2ph[NN * OP];
__device__ __align__(16) __half g_acc2ph[NN * OP];
__device__ float g_as2[NN];
__device__ float g_ad2[NN];
__device__ float g_den2[NN];

__device__ float g_pool[NG * OUTC];
__device__ float g_cnt[NG];

// ---------------- helpers ----------------
__device__ __forceinline__ float lrelu(float v) { return v > 0.0f ? v : NEG_SLOPE * v; }
__device__ __forceinline__ float elu(float v)   { return v > 0.0f ? v : expm1f(v); }

__device__ __forceinline__ void mma16816(float c[4],
                                         unsigned a0, unsigned a1, unsigned a2, unsigned a3,
                                         unsigned b0, unsigned b1) {
    asm volatile("mma.sync.aligned.m16n8k16.row.col.f32.f16.f16.f32 "
                 "{%0,%1,%2,%3}, {%4,%5,%6,%7}, {%8,%9}, {%0,%1,%2,%3};"
                 : "+f"(c[0]), "+f"(c[1]), "+f"(c[2]), "+f"(c[3])
                 : "r"(a0), "r"(a1), "r"(a2), "r"(a3), "r"(b0), "r"(b1));
}

// ---------------- weight convert: W1 -> [n][k] fp16, W2 -> [n16][k] fp16 ----------------
__global__ void convert_w_kernel(const float* __restrict__ W1, const float* __restrict__ W2) {
    int t = blockIdx.x * blockDim.x + threadIdx.x;
    if (t < F1 * F1) {
        int n = t >> 7, k = t & 127;
        g_W1h[t] = __float2half(W1[k * F1 + n]);
    } else if (t < F1 * F1 + OP * F1) {
        int i = t - F1 * F1;
        int n = i >> 7, k = i & 127;
        g_W2h[i] = (n < OUTC) ? __float2half(W2[k * OUTC + n]) : __half(0);
    }
}

// ---------------- GEMM1 (tensor core) + fused attention dots ----------------
__global__ void gemm1_att_kernel(const float* __restrict__ x,
                                 const float* __restrict__ att_s,
                                 const float* __restrict__ att_d) {
    extern __shared__ __half smem[];
    __half* Wt = smem;                    // [128][WS]
    __half* xs = smem + F1 * WS;          // [64][XS], later reused as output staging
    float* satt = (float*)(xs + 64 * XS); // [256]: att_s | att_d

    int t = threadIdx.x;
    int row0 = blockIdx.x * 64;

    const uint4* wsrc = (const uint4*)g_W1h;
    for (int i = t; i < F1 * F1 / 8; i += 256) {
        int n = i >> 4, kc = (i & 15) * 8;
        *(uint4*)&Wt[n * WS + kc] = wsrc[i];
    }
    const float4* xv = (const float4*)x;
    for (int i = t; i < 64 * 32; i += 256) {
        int r = i >> 5, c4 = i & 31;
        int gr = row0 + r;
        float4 v = (gr < NN) ? xv[gr * 32 + c4] : make_float4(0, 0, 0, 0);
        __half2 h0 = __floats2half2_rn(v.x, v.y);
        __half2 h1 = __floats2half2_rn(v.z, v.w);
        *(__half2*)&xs[r * XS + c4 * 4]     = h0;
        *(__half2*)&xs[r * XS + c4 * 4 + 2] = h1;
    }
    if (t < 128) { satt[t] = att_s[t]; satt[128 + t] = att_d[t]; }
    __syncthreads();

    int wid = t >> 5, lane = t & 31;
    int wm = wid & 3, wn = wid >> 2;
    int rq = lane >> 2;
    int q2 = (lane & 3) * 2;
    int rA = wm * 16 + rq;

    float c[8][4];
#pragma unroll
    for (int nt = 0; nt < 8; nt++)
#pragma unroll
        for (int j = 0; j < 4; j++) c[nt][j] = 0.0f;

#pragma unroll
    for (int kb = 0; kb < F1; kb += 16) {
        unsigned a0 = *(unsigned*)&xs[rA * XS + kb + q2];
        unsigned a1 = *(unsigned*)&xs[(rA + 8) * XS + kb + q2];
        unsigned a2 = *(unsigned*)&xs[rA * XS + kb + q2 + 8];
        unsigned a3 = *(unsigned*)&xs[(rA + 8) * XS + kb + q2 + 8];
#pragma unroll
        for (int nt = 0; nt < 8; nt++) {
            int n = wn * 64 + nt * 8 + rq;
            unsigned b0 = *(unsigned*)&Wt[n * WS + kb + q2];
            unsigned b1 = *(unsigned*)&Wt[n * WS + kb + q2 + 8];
            mma16816(c[nt], a0, a1, a2, a3, b0, b1);
        }
    }

    __syncthreads();
    __half* es = xs;
#pragma unroll
    for (int nt = 0; nt < 8; nt++) {
        int col = wn * 64 + nt * 8 + q2;
        *(__half2*)&es[rA * XS + col]       = __floats2half2_rn(c[nt][0], c[nt][1]);
        *(__half2*)&es[(rA + 8) * XS + col] = __floats2half2_rn(c[nt][2], c[nt][3]);
    }
    __syncthreads();

    {
        int row = t >> 2, head = t & 3;
        int grow = row0 + row;
        if (grow < NN) {
            float s = 0.0f, d = 0.0f;
#pragma unroll
            for (int i = 0; i < 16; i++) {
                float2 f = __half22float2(*(__half2*)&es[row * XS + head * 32 + i * 2]);
                s += f.x * satt[head * 32 + i * 2] + f.y * satt[head * 32 + i * 2 + 1];
                d += f.x * satt[128 + head * 32 + i * 2] + f.y * satt[128 + head * 32 + i * 2 + 1];
            }
            g_as1[grow * H1 + head] = s;
            g_ad1[grow * H1 + head] = d;
        }
    }
#pragma unroll
    for (int j = 0; j < 4; j++) {
        int idx = t * 4 + j;
        int r2 = idx >> 4, c8 = (idx & 15) * 8;
        int gr = row0 + r2;
        if (gr < NN)
            *(uint4*)&g_h1h[gr * F1 + c8] = *(uint4*)&es[r2 * XS + c8];
    }
}

// ---------------- edge accumulate layer1: 8 lanes per edge ----------------
__global__ void edge_acc1_kernel(const int* __restrict__ ei, int E_real, int E_tot) {
    int warp = (blockIdx.x * blockDim.x + threadIdx.x) >> 5;
    int lane = threadIdx.x & 31;
    int sub = lane >> 3;       // edge slot 0..3
    int sl  = lane & 7;
    int e = warp * 4 + sub;
    bool act = (e < E_tot);

    int v = 0;
    if (lane < 8) {
        int ee = warp * 4 + (lane >> 1);
        if (ee < E_real)      v = __ldg(&ei[ee + ((lane & 1) ? E_real : 0)]);
        else if (ee < E_tot)  v = ee - E_real;
    }
    int s = __shfl_sync(0xffffffffu, v, sub * 2);
    int d = __shfl_sync(0xffffffffu, v, sub * 2 + 1);

    float ex = 0.0f;
    if (act && sl < H1) {
        float val = lrelu(g_as1[s * H1 + sl] + g_ad1[d * H1 + sl]);
        ex = __expf(val);
        atomicAdd(&g_den1[d * H1 + sl], ex);
    }
    float exl = __shfl_sync(0xffffffffu, ex, sub * 8 + (sl >> 1));  // head = sl/2
    __half2 ex2 = __float2half2_rn(exl);

    const uint4* hp = (const uint4*)&g_h1h[s * F1 + sl * 16];
    uint4 r0 = __ldg(hp);
    uint4 r1 = __ldg(hp + 1);
    __half2 m0 = __hmul2(*(__half2*)&r0.x, ex2);
    __half2 m1 = __hmul2(*(__half2*)&r0.y, ex2);
    __half2 m2 = __hmul2(*(__half2*)&r0.z, ex2);
    __half2 m3 = __hmul2(*(__half2*)&r0.w, ex2);
    __half2 m4 = __hmul2(*(__half2*)&r1.x, ex2);
    __half2 m5 = __hmul2(*(__half2*)&r1.y, ex2);
    __half2 m6 = __hmul2(*(__half2*)&r1.z, ex2);
    __half2 m7 = __hmul2(*(__half2*)&r1.w, ex2);
    if (act) {
        __half* dst = &g_acc1h[d * F1 + sl * 16];
        asm volatile("red.global.add.noftz.v4.f16x2 [%0], {%1,%2,%3,%4};"
                     :: "l"(dst), "r"(*(unsigned*)&m0), "r"(*(unsigned*)&m1),
                        "r"(*(unsigned*)&m2), "r"(*(unsigned*)&m3) : "memory");
        asm volatile("red.global.add.noftz.v4.f16x2 [%0], {%1,%2,%3,%4};"
                     :: "l"(dst + 8), "r"(*(unsigned*)&m4), "r"(*(unsigned*)&m5),
                        "r"(*(unsigned*)&m6), "r"(*(unsigned*)&m7) : "memory");
    }
}

// ---------------- layer2 node: dequant+elu -> mma @W2 -> att2 dots ----------------
__global__ void l2gemm_kernel(const float* __restrict__ b1,
                              const float* __restrict__ att_s2,
                              const float* __restrict__ att_d2) {
    __shared__ __half hs[64 * XS];
    __shared__ __half w2s[OP * WS];
    __shared__ float es[64 * 20];
    __shared__ float b1s[F1];
    __shared__ float satt[2 * OUTC];

    int t = threadIdx.x;
    int row0 = blockIdx.x * 64;

    const uint4* wsrc = (const uint4*)g_W2h;
    for (int i = t; i < OP * F1 / 8; i += 256) {
        int n = i >> 4, kc = (i & 15) * 8;
        *(uint4*)&w2s[n * WS + kc] = wsrc[i];
    }
    if (t < F1) b1s[t] = b1[t];
    if (t >= 128 && t < 128 + OUTC) satt[t - 128] = att_s2[t - 128];
    if (t >= 160 && t < 160 + OUTC) satt[OUTC + t - 160] = att_d2[t - 160];
    __syncthreads();

    // dequant + elu into hs
#pragma unroll
    for (int j = 0; j < 4; j++) {
        int chunk = j * 256 + t;            // 0..1023
        int r = chunk >> 4, part = chunk & 15;
        int ch0 = part * 8;
        int gr = row0 + r;
        uint4 raw = make_uint4(0, 0, 0, 0);
        float inv = 0.0f;
        if (gr < NN) {
            raw = *(const uint4*)&g_acc1h[gr * F1 + ch0];
            inv = 1.0f / (g_den1[gr * H1 + (part >> 2)] + 1e-16f);
        }
        const unsigned* rw = (const unsigned*)&raw;
        __half2 outp[4];
#pragma unroll
        for (int q = 0; q < 4; q++) {
            float2 f = __half22float2(*(__half2*)&rw[q]);
            float h0 = elu(f.x * inv + b1s[ch0 + q * 2]);
            float h1 = elu(f.y * inv + b1s[ch0 + q * 2 + 1]);
            outp[q] = __floats2half2_rn(h0, h1);
        }
        *(uint4*)&hs[r * XS + ch0] = *(uint4*)outp;
    }
    __syncthreads();

    int wid = t >> 5, lane = t & 31;
    int wm = wid & 3, wn = wid >> 2;     // 4 m-tiles x 2 n-tiles (n=8 each)
    int rq = lane >> 2;
    int q2 = (lane & 3) * 2;
    int rA = wm * 16 + rq;

    float c[4] = {0, 0, 0, 0};
#pragma unroll
    for (int kb = 0; kb < F1; kb += 16) {
        unsigned a0 = *(unsigned*)&hs[rA * XS + kb + q2];
        unsigned a1 = *(unsigned*)&hs[(rA + 8) * XS + kb + q2];
        unsigned a2 = *(unsigned*)&hs[rA * XS + kb + q2 + 8];
        unsigned a3 = *(unsigned*)&hs[(rA + 8) * XS + kb + q2 + 8];
        int n = wn * 8 + rq;
        unsigned b0 = *(unsigned*)&w2s[n * WS + kb + q2];
        unsigned b1r = *(unsigned*)&w2s[n * WS + kb + q2 + 8];
        mma16816(c, a0, a1, a2, a3, b0, b1r);
    }
    {
        int col = wn * 8 + q2;
        es[rA * 20 + col]           = c[0];
        es[rA * 20 + col + 1]       = c[1];
        es[(rA + 8) * 20 + col]     = c[2];
        es[(rA + 8) * 20 + col + 1] = c[3];
    }
    __syncthreads();

    if (t < 64) {
        int gr = row0 + t;
        if (gr < NN) {
            float as = 0.0f, ad = 0.0f;
            __half2 pk[8];
#pragma unroll
            for (int c2 = 0; c2 < 8; c2++) {
                float lo = (2 * c2 < OUTC)     ? es[t * 20 + 2 * c2]     : 0.0f;
                float hi = (2 * c2 + 1 < OUTC) ? es[t * 20 + 2 * c2 + 1] : 0.0f;
                pk[c2] = __floats2half2_rn(lo, hi);
                if (2 * c2 < OUTC)     { as += lo * satt[2 * c2];     ad += lo * satt[OUTC + 2 * c2]; }
                if (2 * c2 + 1 < OUTC) { as += hi * satt[2 * c2 + 1]; ad += hi * satt[OUTC + 2 * c2 + 1]; }
            }
            *(uint4*)&g_h2ph[gr * OP]     = *(uint4*)&pk[0];
            *(uint4*)&g_h2ph[gr * OP + 8] = *(uint4*)&pk[4];
            g_as2[gr] = as;
            g_ad2[gr] = ad;
        }
    }
}

// ---------------- edge accumulate layer2: 2 lanes per edge ----------------
__global__ void edge_acc2_kernel(const int* __restrict__ ei, int E_real, int E_tot) {
    int warp = (blockIdx.x * blockDim.x + threadIdx.x) >> 5;
    int lane = threadIdx.x & 31;
    int li = lane & 1;
    int ee = warp * 16 + (lane >> 1);
    bool act = (ee < E_tot);

    int v = 0;
    if (ee < E_real)     v = __ldg(&ei[ee + (li ? E_real : 0)]);
    else if (ee < E_tot) v = ee - E_real;
    int s = __shfl_sync(0xffffffffu, v, lane & ~1);
    int d = __shfl_sync(0xffffffffu, v, lane | 1);

    float ex = 0.0f;
    if (act && li == 0) {
        ex = __expf(lrelu(g_as2[s] + g_ad2[d]));
        atomicAdd(&g_den2[d], ex);
    }
    ex = __shfl_sync(0xffffffffu, ex, lane & ~1);
    __half2 ex2 = __float2half2_rn(ex);
    uint4 raw = __ldg((const uint4*)&g_h2ph[s * OP + li * 8]);
    __half2 m0 = __hmul2(*(__half2*)&raw.x, ex2);
    __half2 m1 = __hmul2(*(__half2*)&raw.y, ex2);
    __half2 m2 = __hmul2(*(__half2*)&raw.z, ex2);
    __half2 m3 = __hmul2(*(__half2*)&raw.w, ex2);
    if (act) {
        __half* dst = &g_acc2ph[d * OP + li * 8];
        asm volatile("red.global.add.noftz.v4.f16x2 [%0], {%1,%2,%3,%4};"
                     :: "l"(dst), "r"(*(unsigned*)&m0), "r"(*(unsigned*)&m1),
                        "r"(*(unsigned*)&m2), "r"(*(unsigned*)&m3) : "memory");
    }
}

// ---------------- finalize layer2 + pooling ----------------
__global__ void fin2pool_kernel(const float* __restrict__ b2, const int* __restrict__ batch) {
    int n = blockIdx.x * blockDim.x + threadIdx.x;
    if (n >= NN) return;
    float inv = 1.0f / (g_den2[n] + 1e-16f);
    int g = batch[n];
#pragma unroll
    for (int c = 0; c < OUTC; c++) {
        float v = elu(__half2float(g_acc2ph[n * OP + c]) * inv + b2[c]);
        atomicAdd(&g_pool[g * OUTC + c], v);
    }
    atomicAdd(&g_cnt[g], 1.0f);
}

// ---------------- final: mean + log_softmax ----------------
__global__ void final_kernel(float* __restrict__ out) {
    int g = threadIdx.x;
    if (g >= NG) return;
    float cnt = fmaxf(g_cnt[g], 1.0f);
    float p[OUTC];
    float mx = -CUDART_INF_F;
#pragma unroll
    for (int c = 0; c < OUTC; c++) {
        p[c] = g_pool[g * OUTC + c] / cnt;
        mx = fmaxf(mx, p[c]);
    }
    float se = 0.0f;
#pragma unroll
    for (int c = 0; c < OUTC; c++) se += expf(p[c] - mx);
    float lse = mx + logf(se);
#pragma unroll
    for (int c = 0; c < OUTC; c++) out[g * OUTC + c] = p[c] - lse;
}

// ---------------- launch ----------------
extern "C" void kernel_launch(void* const* d_in, const int* in_sizes, int n_in,
                              void* d_out, int out_size) {
    const float* x      = (const float*)d_in[0];
    const float* W1     = (const float*)d_in[1];
    const float* att_s1 = (const float*)d_in[2];
    const float* att_d1 = (const float*)d_in[3];
    const float* b1     = (const float*)d_in[4];
    const float* W2     = (const float*)d_in[5];
    const float* att_s2 = (const float*)d_in[6];
    const float* att_d2 = (const float*)d_in[7];
    const float* b2     = (const float*)d_in[8];
    const int*   ei     = (const int*)d_in[9];
    const int*   batch  = (const int*)d_in[10];
    float* out = (float*)d_out;

    int E_real = in_sizes[9] / 2;
    int E_tot = E_real + NN;

    void *p_acc1, *p_den1, *p_acc2, *p_den2, *p_pool, *p_cnt;
    cudaGetSymbolAddress(&p_acc1, g_acc1h);
    cudaGetSymbolAddress(&p_den1, g_den1);
    cudaGetSymbolAddress(&p_acc2, g_acc2ph);
    cudaGetSymbolAddress(&p_den2, g_den2);
    cudaGetSymbolAddress(&p_pool, g_pool);
    cudaGetSymbolAddress(&p_cnt,  g_cnt);

    cudaMemsetAsync(p_acc1, 0, (size_t)NN * F1 * sizeof(__half));
    cudaMemsetAsync(p_den1, 0, (size_t)NN * H1 * sizeof(float));
    cudaMemsetAsync(p_acc2, 0, (size_t)NN * OP * sizeof(__half));
    cudaMemsetAsync(p_den2, 0, (size_t)NN * sizeof(float));
    cudaMemsetAsync(p_pool, 0, (size_t)NG * OUTC * sizeof(float));
    cudaMemsetAsync(p_cnt,  0, (size_t)NG * sizeof(float));

    convert_w_kernel<<<(F1 * F1 + OP * F1 + 255) / 256, 256>>>(W1, W2);

    int gemm_smem = (F1 * WS + 64 * XS) * (int)sizeof(__half) + 256 * (int)sizeof(float);
    cudaFuncSetAttribute(gemm1_att_kernel, cudaFuncAttributeMaxDynamicSharedMemorySize, gemm_smem);
    gemm1_att_kernel<<<(NN + 63) / 64, 256, gemm_smem>>>(x, att_s1, att_d1);

    long long w1 = ((long long)E_tot + 3) / 4;
    edge_acc1_kernel<<<(int)((w1 * 32 + 255) / 256), 256>>>(ei, E_real, E_tot);

    l2gemm_kernel<<<(NN + 63) / 64, 256>>>(b1, att_s2, att_d2);

    long long w2 = ((long long)E_tot + 15) / 16;
    edge_acc2_kernel<<<(int)((w2 * 32 + 255) / 256), 256>>>(ei, E_real, E_tot);

    fin2pool_kernel<<<(NN + 255) / 256, 256>>>(b2, batch);

    final_kernel<<<1, NG>>>(out);
}

// round 7
// speedup vs baseline: 1.5104x; 1.0306x over previous
#include <cuda_runtime.h>
#include <cuda_fp16.h>
#include <math.h>
#include <math_constants.h>

#define NN 100000
#define F1 128
#define H1 4
#define OUTC 10
#define OP 16
#define NG 128
#define NEG_SLOPE 0.2f

#define XS 136   // padded smem stride (halves)
#define WS 136

// ---------------- scratch ----------------
__device__ __align__(16) __half g_h1h[NN * F1];    // layer1 features, fp16
__device__ __align__(16) __half g_acc1h[NN * F1];  // fp16 atomic accumulator (init = self-loop term)
__device__ __align__(16) float  g_as1[NN * H1];
__device__ __align__(16) float  g_ad1[NN * H1];
__device__ __align__(16) float  g_den1[NN * H1];

__device__ __align__(16) __half g_W1h[F1 * F1];    // W1 transposed [n][k], fp16
__device__ __align__(16) __half g_W2h[OP * F1];    // W2 transposed [n16][k], fp16

__device__ __align__(16) __half g_h2ph[NN * OP];
__device__ __align__(16) __half g_acc2ph[NN * OP];
__device__ float g_as2[NN];
__device__ float g_ad2[NN];
__device__ float g_den2[NN];

__device__ float g_pool[NG * OUTC];
__device__ float g_cnt[NG];

// ---------------- helpers ----------------
__device__ __forceinline__ float lrelu(float v) { return v > 0.0f ? v : NEG_SLOPE * v; }
__device__ __forceinline__ float elu(float v)   { return v > 0.0f ? v : expm1f(v); }

__device__ __forceinline__ void mma16816(float c[4],
                                         unsigned a0, unsigned a1, unsigned a2, unsigned a3,
                                         unsigned b0, unsigned b1) {
    asm volatile("mma.sync.aligned.m16n8k16.row.col.f32.f16.f16.f32 "
                 "{%0,%1,%2,%3}, {%4,%5,%6,%7}, {%8,%9}, {%0,%1,%2,%3};"
                 : "+f"(c[0]), "+f"(c[1]), "+f"(c[2]), "+f"(c[3])
                 : "r"(a0), "r"(a1), "r"(a2), "r"(a3), "r"(b0), "r"(b1));
}

// ---------------- weight convert ----------------
__global__ void convert_w_kernel(const float* __restrict__ W1, const float* __restrict__ W2) {
    int t = blockIdx.x * blockDim.x + threadIdx.x;
    if (t < F1 * F1) {
        int n = t >> 7, k = t & 127;
        g_W1h[t] = __float2half(W1[k * F1 + n]);
    } else if (t < F1 * F1 + OP * F1) {
        int i = t - F1 * F1;
        int n = i >> 7, k = i & 127;
        g_W2h[i] = (n < OUTC) ? __float2half(W2[k * OUTC + n]) : __half(0);
    }
}

// ---------------- GEMM1 (tensor core) + attention dots + self-loop init ----------------
__global__ void gemm1_att_kernel(const float* __restrict__ x,
                                 const float* __restrict__ att_s,
                                 const float* __restrict__ att_d) {
    extern __shared__ __half smem[];
    __half* Wt = smem;                    // [128][WS]
    __half* xs = smem + F1 * WS;          // [64][XS], later reused as output staging
    float* satt = (float*)(xs + 64 * XS); // [256]: att_s | att_d
    float* exs  = satt + 256;             // [64*4] self-loop exp per (row, head)

    int t = threadIdx.x;
    int row0 = blockIdx.x * 64;

    const uint4* wsrc = (const uint4*)g_W1h;
    for (int i = t; i < F1 * F1 / 8; i += 256) {
        int n = i >> 4, kc = (i & 15) * 8;
        *(uint4*)&Wt[n * WS + kc] = wsrc[i];
    }
    const float4* xv = (const float4*)x;
    for (int i = t; i < 64 * 32; i += 256) {
        int r = i >> 5, c4 = i & 31;
        int gr = row0 + r;
        float4 v = (gr < NN) ? xv[gr * 32 + c4] : make_float4(0, 0, 0, 0);
        __half2 h0 = __floats2half2_rn(v.x, v.y);
        __half2 h1 = __floats2half2_rn(v.z, v.w);
        *(__half2*)&xs[r * XS + c4 * 4]     = h0;
        *(__half2*)&xs[r * XS + c4 * 4 + 2] = h1;
    }
    if (t < 128) { satt[t] = att_s[t]; satt[128 + t] = att_d[t]; }
    __syncthreads();

    int wid = t >> 5, lane = t & 31;
    int wm = wid & 3, wn = wid >> 2;
    int rq = lane >> 2;
    int q2 = (lane & 3) * 2;
    int rA = wm * 16 + rq;

    float c[8][4];
#pragma unroll
    for (int nt = 0; nt < 8; nt++)
#pragma unroll
        for (int j = 0; j < 4; j++) c[nt][j] = 0.0f;

#pragma unroll
    for (int kb = 0; kb < F1; kb += 16) {
        unsigned a0 = *(unsigned*)&xs[rA * XS + kb + q2];
        unsigned a1 = *(unsigned*)&xs[(rA + 8) * XS + kb + q2];
        unsigned a2 = *(unsigned*)&xs[rA * XS + kb + q2 + 8];
        unsigned a3 = *(unsigned*)&xs[(rA + 8) * XS + kb + q2 + 8];
#pragma unroll
        for (int nt = 0; nt < 8; nt++) {
            int n = wn * 64 + nt * 8 + rq;
            unsigned b0 = *(unsigned*)&Wt[n * WS + kb + q2];
            unsigned b1 = *(unsigned*)&Wt[n * WS + kb + q2 + 8];
            mma16816(c[nt], a0, a1, a2, a3, b0, b1);
        }
    }

    __syncthreads();
    __half* es = xs;
#pragma unroll
    for (int nt = 0; nt < 8; nt++) {
        int col = wn * 64 + nt * 8 + q2;
        *(__half2*)&es[rA * XS + col]       = __floats2half2_rn(c[nt][0], c[nt][1]);
        *(__half2*)&es[(rA + 8) * XS + col] = __floats2half2_rn(c[nt][2], c[nt][3]);
    }
    __syncthreads();

    // attention dots + self-loop exp: thread = (row = t>>2, head = t&3)
    {
        int row = t >> 2, head = t & 3;
        int grow = row0 + row;
        float s = 0.0f, d = 0.0f;
#pragma unroll
        for (int i = 0; i < 16; i++) {
            float2 f = __half22float2(*(__half2*)&es[row * XS + head * 32 + i * 2]);
            s += f.x * satt[head * 32 + i * 2] + f.y * satt[head * 32 + i * 2 + 1];
            d += f.x * satt[128 + head * 32 + i * 2] + f.y * satt[128 + head * 32 + i * 2 + 1];
        }
        float ex = __expf(lrelu(s + d));
        exs[row * 4 + head] = ex;
        if (grow < NN) {
            g_as1[grow * H1 + head] = s;
            g_ad1[grow * H1 + head] = d;
            g_den1[grow * H1 + head] = ex;   // self-loop seeds the denominator
        }
    }
    __syncthreads();

    // h1 store + acc1 init (= ex_self * h1), coalesced
#pragma unroll
    for (int j = 0; j < 4; j++) {
        int idx = t * 4 + j;
        int r2 = idx >> 4, c8 = (idx & 15) * 8;
        int gr = row0 + r2;
        if (gr < NN) {
            uint4 raw = *(uint4*)&es[r2 * XS + c8];
            *(uint4*)&g_h1h[gr * F1 + c8] = raw;
            __half2 ex2 = __float2half2_rn(exs[r2 * 4 + (c8 >> 5)]);
            unsigned* rw = (unsigned*)&raw;
            __half2 a0 = __hmul2(*(__half2*)&rw[0], ex2);
            __half2 a1 = __hmul2(*(__half2*)&rw[1], ex2);
            __half2 a2 = __hmul2(*(__half2*)&rw[2], ex2);
            __half2 a3 = __hmul2(*(__half2*)&rw[3], ex2);
            uint4 out;
            out.x = *(unsigned*)&a0; out.y = *(unsigned*)&a1;
            out.z = *(unsigned*)&a2; out.w = *(unsigned*)&a3;
            *(uint4*)&g_acc1h[gr * F1 + c8] = out;
        }
    }
}

// ---------------- edge accumulate layer1: 8 lanes per edge, real edges only ----------------
__global__ void edge_acc1_kernel(const int* __restrict__ ei, int E_real) {
    int warp = (blockIdx.x * blockDim.x + threadIdx.x) >> 5;
    int lane = threadIdx.x & 31;
    int sub = lane >> 3;
    int sl  = lane & 7;
    int e = warp * 4 + sub;
    bool act = (e < E_real);

    int v = 0;
    if (lane < 8) {
        int ee = warp * 4 + (lane >> 1);
        if (ee < E_real) v = __ldg(&ei[ee + ((lane & 1) ? E_real : 0)]);
    }
    int s = __shfl_sync(0xffffffffu, v, sub * 2);
    int d = __shfl_sync(0xffffffffu, v, sub * 2 + 1);

    float ex = 0.0f;
    if (act && sl < H1) {
        float val = lrelu(g_as1[s * H1 + sl] + g_ad1[d * H1 + sl]);
        ex = __expf(val);
        atomicAdd(&g_den1[d * H1 + sl], ex);
    }
    float exl = __shfl_sync(0xffffffffu, ex, sub * 8 + (sl >> 1));
    __half2 ex2 = __float2half2_rn(exl);

    const uint4* hp = (const uint4*)&g_h1h[s * F1 + sl * 16];
    uint4 r0 = __ldg(hp);
    uint4 r1 = __ldg(hp + 1);
    __half2 m0 = __hmul2(*(__half2*)&r0.x, ex2);
    __half2 m1 = __hmul2(*(__half2*)&r0.y, ex2);
    __half2 m2 = __hmul2(*(__half2*)&r0.z, ex2);
    __half2 m3 = __hmul2(*(__half2*)&r0.w, ex2);
    __half2 m4 = __hmul2(*(__half2*)&r1.x, ex2);
    __half2 m5 = __hmul2(*(__half2*)&r1.y, ex2);
    __half2 m6 = __hmul2(*(__half2*)&r1.z, ex2);
    __half2 m7 = __hmul2(*(__half2*)&r1.w, ex2);
    if (act) {
        __half* dst = &g_acc1h[d * F1 + sl * 16];
        asm volatile("red.global.add.noftz.v4.f16x2 [%0], {%1,%2,%3,%4};"
                     :: "l"(dst), "r"(*(unsigned*)&m0), "r"(*(unsigned*)&m1),
                        "r"(*(unsigned*)&m2), "r"(*(unsigned*)&m3) : "memory");
        asm volatile("red.global.add.noftz.v4.f16x2 [%0], {%1,%2,%3,%4};"
                     :: "l"(dst + 8), "r"(*(unsigned*)&m4), "r"(*(unsigned*)&m5),
                        "r"(*(unsigned*)&m6), "r"(*(unsigned*)&m7) : "memory");
    }
}

// ---------------- layer2 node: dequant+elu -> mma @W2 -> att2 + self-loop init ----------------
__global__ void l2gemm_kernel(const float* __restrict__ b1,
                              const float* __restrict__ att_s2,
                              const float* __restrict__ att_d2) {
    __shared__ __half hs[64 * XS];
    __shared__ __half w2s[OP * WS];
    __shared__ float es[64 * 20];
    __shared__ float b1s[F1];
    __shared__ float satt[2 * OUTC];

    int t = threadIdx.x;
    int row0 = blockIdx.x * 64;

    const uint4* wsrc = (const uint4*)g_W2h;
    for (int i = t; i < OP * F1 / 8; i += 256) {
        int n = i >> 4, kc = (i & 15) * 8;
        *(uint4*)&w2s[n * WS + kc] = wsrc[i];
    }
    if (t < F1) b1s[t] = b1[t];
    if (t >= 128 && t < 128 + OUTC) satt[t - 128] = att_s2[t - 128];
    if (t >= 160 && t < 160 + OUTC) satt[OUTC + t - 160] = att_d2[t - 160];
    __syncthreads();

#pragma unroll
    for (int j = 0; j < 4; j++) {
        int chunk = j * 256 + t;
        int r = chunk >> 4, part = chunk & 15;
        int ch0 = part * 8;
        int gr = row0 + r;
        uint4 raw = make_uint4(0, 0, 0, 0);
        float inv = 0.0f;
        if (gr < NN) {
            raw = *(const uint4*)&g_acc1h[gr * F1 + ch0];
            inv = 1.0f / (g_den1[gr * H1 + (part >> 2)] + 1e-16f);
        }
        const unsigned* rw = (const unsigned*)&raw;
        __half2 outp[4];
#pragma unroll
        for (int q = 0; q < 4; q++) {
            float2 f = __half22float2(*(__half2*)&rw[q]);
            float h0 = elu(f.x * inv + b1s[ch0 + q * 2]);
            float h1 = elu(f.y * inv + b1s[ch0 + q * 2 + 1]);
            outp[q] = __floats2half2_rn(h0, h1);
        }
        *(uint4*)&hs[r * XS + ch0] = *(uint4*)outp;
    }
    __syncthreads();

    int wid = t >> 5, lane = t & 31;
    int wm = wid & 3, wn = wid >> 2;
    int rq = lane >> 2;
    int q2 = (lane & 3) * 2;
    int rA = wm * 16 + rq;

    float c[4] = {0, 0, 0, 0};
#pragma unroll
    for (int kb = 0; kb < F1; kb += 16) {
        unsigned a0 = *(unsigned*)&hs[rA * XS + kb + q2];
        unsigned a1 = *(unsigned*)&hs[(rA + 8) * XS + kb + q2];
        unsigned a2 = *(unsigned*)&hs[rA * XS + kb + q2 + 8];
        unsigned a3 = *(unsigned*)&hs[(rA + 8) * XS + kb + q2 + 8];
        int n = wn * 8 + rq;
        unsigned b0 = *(unsigned*)&w2s[n * WS + kb + q2];
        unsigned b1r = *(unsigned*)&w2s[n * WS + kb + q2 + 8];
        mma16816(c, a0, a1, a2, a3, b0, b1r);
    }
    {
        int col = wn * 8 + q2;
        es[rA * 20 + col]           = c[0];
        es[rA * 20 + col + 1]       = c[1];
        es[(rA + 8) * 20 + col]     = c[2];
        es[(rA + 8) * 20 + col + 1] = c[3];
    }
    __syncthreads();

    if (t < 64) {
        int gr = row0 + t;
        if (gr < NN) {
            float as = 0.0f, ad = 0.0f;
            __half2 pk[8];
#pragma unroll
            for (int c2 = 0; c2 < 8; c2++) {
                float lo = (2 * c2 < OUTC)     ? es[t * 20 + 2 * c2]     : 0.0f;
                float hi = (2 * c2 + 1 < OUTC) ? es[t * 20 + 2 * c2 + 1] : 0.0f;
                pk[c2] = __floats2half2_rn(lo, hi);
                if (2 * c2 < OUTC)     { as += lo * satt[2 * c2];     ad += lo * satt[OUTC + 2 * c2]; }
                if (2 * c2 + 1 < OUTC) { as += hi * satt[2 * c2 + 1]; ad += hi * satt[OUTC + 2 * c2 + 1]; }
            }
            *(uint4*)&g_h2ph[gr * OP]     = *(uint4*)&pk[0];
            *(uint4*)&g_h2ph[gr * OP + 8] = *(uint4*)&pk[4];
            g_as2[gr] = as;
            g_ad2[gr] = ad;
            // self-loop init for layer 2
            float ex = __expf(lrelu(as + ad));
            g_den2[gr] = ex;
            __half2 ex2 = __float2half2_rn(ex);
            __half2 ak[8];
#pragma unroll
            for (int c2 = 0; c2 < 8; c2++) ak[c2] = __hmul2(pk[c2], ex2);
            *(uint4*)&g_acc2ph[gr * OP]     = *(uint4*)&ak[0];
            *(uint4*)&g_acc2ph[gr * OP + 8] = *(uint4*)&ak[4];
        }
    }
}

// ---------------- edge accumulate layer2: 2 lanes per edge, real edges only ----------------
__global__ void edge_acc2_kernel(const int* __restrict__ ei, int E_real) {
    int warp = (blockIdx.x * blockDim.x + threadIdx.x) >> 5;
    int lane = threadIdx.x & 31;
    int li = lane & 1;
    int ee = warp * 16 + (lane >> 1);
    bool act = (ee < E_real);

    int v = 0;
    if (act) v = __ldg(&ei[ee + (li ? E_real : 0)]);
    int s = __shfl_sync(0xffffffffu, v, lane & ~1);
    int d = __shfl_sync(0xffffffffu, v, lane | 1);

    float ex = 0.0f;
    if (act && li == 0) {
        ex = __expf(lrelu(g_as2[s] + g_ad2[d]));
        atomicAdd(&g_den2[d], ex);
    }
    ex = __shfl_sync(0xffffffffu, ex, lane & ~1);
    __half2 ex2 = __float2half2_rn(ex);
    uint4 raw = __ldg((const uint4*)&g_h2ph[s * OP + li * 8]);
    __half2 m0 = __hmul2(*(__half2*)&raw.x, ex2);
    __half2 m1 = __hmul2(*(__half2*)&raw.y, ex2);
    __half2 m2 = __hmul2(*(__half2*)&raw.z, ex2);
    __half2 m3 = __hmul2(*(__half2*)&raw.w, ex2);
    if (act) {
        __half* dst = &g_acc2ph[d * OP + li * 8];
        asm volatile("red.global.add.noftz.v4.f16x2 [%0], {%1,%2,%3,%4};"
                     :: "l"(dst), "r"(*(unsigned*)&m0), "r"(*(unsigned*)&m1),
                        "r"(*(unsigned*)&m2), "r"(*(unsigned*)&m3) : "memory");
    }
}

// ---------------- finalize layer2 + pooling ----------------
__global__ void fin2pool_kernel(const float* __restrict__ b2, const int* __restrict__ batch) {
    int n = blockIdx.x * blockDim.x + threadIdx.x;
    if (n >= NN) return;
    float inv = 1.0f / (g_den2[n] + 1e-16f);
    int g = batch[n];
#pragma unroll
    for (int c = 0; c < OUTC; c++) {
        float v = elu(__half2float(g_acc2ph[n * OP + c]) * inv + b2[c]);
        atomicAdd(&g_pool[g * OUTC + c], v);
    }
    atomicAdd(&g_cnt[g], 1.0f);
}

// ---------------- final: mean + log_softmax ----------------
__global__ void final_kernel(float* __restrict__ out) {
    int g = threadIdx.x;
    if (g >= NG) return;
    float cnt = fmaxf(g_cnt[g], 1.0f);
    float p[OUTC];
    float mx = -CUDART_INF_F;
#pragma unroll
    for (int c = 0; c < OUTC; c++) {
        p[c] = g_pool[g * OUTC + c] / cnt;
        mx = fmaxf(mx, p[c]);
    }
    float se = 0.0f;
#pragma unroll
    for (int c = 0; c < OUTC; c++) se += expf(p[c] - mx);
    float lse = mx + logf(se);
#pragma unroll
    for (int c = 0; c < OUTC; c++) out[g * OUTC + c] = p[c] - lse;
}

// ---------------- launch ----------------
extern "C" void kernel_launch(void* const* d_in, const int* in_sizes, int n_in,
                              void* d_out, int out_size) {
    const float* x      = (const float*)d_in[0];
    const float* W1     = (const float*)d_in[1];
    const float* att_s1 = (const float*)d_in[2];
    const float* att_d1 = (const float*)d_in[3];
    const float* b1     = (const float*)d_in[4];
    const float* W2     = (const float*)d_in[5];
    const float* att_s2 = (const float*)d_in[6];
    const float* att_d2 = (const float*)d_in[7];
    const float* b2     = (const float*)d_in[8];
    const int*   ei     = (const int*)d_in[9];
    const int*   batch  = (const int*)d_in[10];
    float* out = (float*)d_out;

    int E_real = in_sizes[9] / 2;

    void *p_pool, *p_cnt;
    cudaGetSymbolAddress(&p_pool, g_pool);
    cudaGetSymbolAddress(&p_cnt,  g_cnt);
    cudaMemsetAsync(p_pool, 0, (size_t)NG * OUTC * sizeof(float));
    cudaMemsetAsync(p_cnt,  0, (size_t)NG * sizeof(float));

    convert_w_kernel<<<(F1 * F1 + OP * F1 + 255) / 256, 256>>>(W1, W2);

    int gemm_smem = (F1 * WS + 64 * XS) * (int)sizeof(__half) + 512 * (int)sizeof(float);
    cudaFuncSetAttribute(gemm1_att_kernel, cudaFuncAttributeMaxDynamicSharedMemorySize, gemm_smem);
    gemm1_att_kernel<<<(NN + 63) / 64, 256, gemm_smem>>>(x, att_s1, att_d1);

    long long w1 = ((long long)E_real + 3) / 4;
    edge_acc1_kernel<<<(int)((w1 * 32 + 255) / 256), 256>>>(ei, E_real);

    l2gemm_kernel<<<(NN + 63) / 64, 256>>>(b1, att_s2, att_d2);

    long long w2 = ((long long)E_real + 15) / 16;
    edge_acc2_kernel<<<(int)((w2 * 32 + 255) / 256), 256>>>(ei, E_real);

    fin2pool_kernel<<<(NN + 255) / 256, 256>>>(b2, batch);

    final_kernel<<<1, NG>>>(out);
}

// round 8
// speedup vs baseline: 2.0905x; 1.3840x over previous
#include <cuda_runtime.h>
#include <cuda_fp16.h>
#include <math.h>
#include <math_constants.h>

#define NN 100000
#define F1 128
#define H1 4
#define OUTC 10
#define OP 16
#define NG 128
#define NEG_SLOPE 0.2f

#define XS 136   // padded smem stride (halves)
#define WS 136

// ---------------- scratch ----------------
__device__ __align__(16) __half g_h1h[NN * F1];    // layer1 features, fp16
__device__ __align__(16) __half g_acc1h[NN * F1];  // fp16 atomic accumulator (init = self-loop term)
__device__ __align__(16) float  g_as1[NN * H1];
__device__ __align__(16) float  g_ad1[NN * H1];
__device__ __align__(16) float  g_den1[NN * H1];

__device__ __align__(16) __half g_W1h[F1 * F1];    // W1 transposed [n][k], fp16
__device__ __align__(16) __half g_W2h[OP * F1];    // W2 transposed [n16][k], fp16

__device__ __align__(16) __half g_h2ph[NN * OP];
__device__ __align__(16) __half g_acc2ph[NN * OP];
__device__ float g_as2[NN];
__device__ float g_ad2[NN];
__device__ float g_den2[NN];

__device__ float g_pool[NG * OUTC];
__device__ float g_cnt[NG];

// ---------------- helpers ----------------
__device__ __forceinline__ float lrelu(float v) { return v > 0.0f ? v : NEG_SLOPE * v; }
__device__ __forceinline__ float elu_fast(float v) { return v > 0.0f ? v : (__expf(v) - 1.0f); }

__device__ __forceinline__ void mma16816(float c[4],
                                         unsigned a0, unsigned a1, unsigned a2, unsigned a3,
                                         unsigned b0, unsigned b1) {
    asm volatile("mma.sync.aligned.m16n8k16.row.col.f32.f16.f16.f32 "
                 "{%0,%1,%2,%3}, {%4,%5,%6,%7}, {%8,%9}, {%0,%1,%2,%3};"
                 : "+f"(c[0]), "+f"(c[1]), "+f"(c[2]), "+f"(c[3])
                 : "r"(a0), "r"(a1), "r"(a2), "r"(a3), "r"(b0), "r"(b1));
}

// ---------------- weight convert ----------------
__global__ void convert_w_kernel(const float* __restrict__ W1, const float* __restrict__ W2) {
    int t = blockIdx.x * blockDim.x + threadIdx.x;
    if (t < F1 * F1) {
        int n = t >> 7, k = t & 127;
        g_W1h[t] = __float2half(W1[k * F1 + n]);
    } else if (t < F1 * F1 + OP * F1) {
        int i = t - F1 * F1;
        int n = i >> 7, k = i & 127;
        g_W2h[i] = (n < OUTC) ? __float2half(W2[k * OUTC + n]) : __half(0);
    }
}

// ---------------- GEMM1 (tensor core) + attention dots + self-loop init ----------------
__global__ void gemm1_att_kernel(const float* __restrict__ x,
                                 const float* __restrict__ att_s,
                                 const float* __restrict__ att_d) {
    extern __shared__ __half smem[];
    __half* Wt = smem;                    // [128][WS]
    __half* xs = smem + F1 * WS;          // [64][XS], later reused as output staging
    float* satt = (float*)(xs + 64 * XS); // [256]: att_s | att_d
    float* exs  = satt + 256;             // [64*4] self-loop exp per (row, head)

    int t = threadIdx.x;
    int row0 = blockIdx.x * 64;

    const uint4* wsrc = (const uint4*)g_W1h;
    for (int i = t; i < F1 * F1 / 8; i += 256) {
        int n = i >> 4, kc = (i & 15) * 8;
        *(uint4*)&Wt[n * WS + kc] = wsrc[i];
    }
    const float4* xv = (const float4*)x;
    for (int i = t; i < 64 * 32; i += 256) {
        int r = i >> 5, c4 = i & 31;
        int gr = row0 + r;
        float4 v = (gr < NN) ? xv[gr * 32 + c4] : make_float4(0, 0, 0, 0);
        __half2 h0 = __floats2half2_rn(v.x, v.y);
        __half2 h1 = __floats2half2_rn(v.z, v.w);
        *(__half2*)&xs[r * XS + c4 * 4]     = h0;
        *(__half2*)&xs[r * XS + c4 * 4 + 2] = h1;
    }
    if (t < 128) { satt[t] = att_s[t]; satt[128 + t] = att_d[t]; }
    __syncthreads();

    int wid = t >> 5, lane = t & 31;
    int wm = wid & 3, wn = wid >> 2;
    int rq = lane >> 2;
    int q2 = (lane & 3) * 2;
    int rA = wm * 16 + rq;

    float c[8][4];
#pragma unroll
    for (int nt = 0; nt < 8; nt++)
#pragma unroll
        for (int j = 0; j < 4; j++) c[nt][j] = 0.0f;

#pragma unroll
    for (int kb = 0; kb < F1; kb += 16) {
        unsigned a0 = *(unsigned*)&xs[rA * XS + kb + q2];
        unsigned a1 = *(unsigned*)&xs[(rA + 8) * XS + kb + q2];
        unsigned a2 = *(unsigned*)&xs[rA * XS + kb + q2 + 8];
        unsigned a3 = *(unsigned*)&xs[(rA + 8) * XS + kb + q2 + 8];
#pragma unroll
        for (int nt = 0; nt < 8; nt++) {
            int n = wn * 64 + nt * 8 + rq;
            unsigned b0 = *(unsigned*)&Wt[n * WS + kb + q2];
            unsigned b1 = *(unsigned*)&Wt[n * WS + kb + q2 + 8];
            mma16816(c[nt], a0, a1, a2, a3, b0, b1);
        }
    }

    __syncthreads();
    __half* es = xs;
#pragma unroll
    for (int nt = 0; nt < 8; nt++) {
        int col = wn * 64 + nt * 8 + q2;
        *(__half2*)&es[rA * XS + col]       = __floats2half2_rn(c[nt][0], c[nt][1]);
        *(__half2*)&es[(rA + 8) * XS + col] = __floats2half2_rn(c[nt][2], c[nt][3]);
    }
    __syncthreads();

    {
        int row = t >> 2, head = t & 3;
        int grow = row0 + row;
        float s = 0.0f, d = 0.0f;
#pragma unroll
        for (int i = 0; i < 16; i++) {
            float2 f = __half22float2(*(__half2*)&es[row * XS + head * 32 + i * 2]);
            s += f.x * satt[head * 32 + i * 2] + f.y * satt[head * 32 + i * 2 + 1];
            d += f.x * satt[128 + head * 32 + i * 2] + f.y * satt[128 + head * 32 + i * 2 + 1];
        }
        float ex = __expf(lrelu(s + d));
        exs[row * 4 + head] = ex;
        if (grow < NN) {
            g_as1[grow * H1 + head] = s;
            g_ad1[grow * H1 + head] = d;
            g_den1[grow * H1 + head] = ex;
        }
    }
    __syncthreads();

#pragma unroll
    for (int j = 0; j < 4; j++) {
        int idx = t * 4 + j;
        int r2 = idx >> 4, c8 = (idx & 15) * 8;
        int gr = row0 + r2;
        if (gr < NN) {
            uint4 raw = *(uint4*)&es[r2 * XS + c8];
            *(uint4*)&g_h1h[gr * F1 + c8] = raw;
            __half2 ex2 = __float2half2_rn(exs[r2 * 4 + (c8 >> 5)]);
            unsigned* rw = (unsigned*)&raw;
            __half2 a0 = __hmul2(*(__half2*)&rw[0], ex2);
            __half2 a1 = __hmul2(*(__half2*)&rw[1], ex2);
            __half2 a2 = __hmul2(*(__half2*)&rw[2], ex2);
            __half2 a3 = __hmul2(*(__half2*)&rw[3], ex2);
            uint4 out;
            out.x = *(unsigned*)&a0; out.y = *(unsigned*)&a1;
            out.z = *(unsigned*)&a2; out.w = *(unsigned*)&a3;
            *(uint4*)&g_acc1h[gr * F1 + c8] = out;
        }
    }
}

// ---------------- edge accumulate layer1: 8 lanes per edge ----------------
__global__ void edge_acc1_kernel(const int* __restrict__ ei, int E_real) {
    int warp = (blockIdx.x * blockDim.x + threadIdx.x) >> 5;
    int lane = threadIdx.x & 31;
    int sub = lane >> 3;
    int sl  = lane & 7;
    int e = warp * 4 + sub;
    bool act = (e < E_real);

    int v = 0;
    if (lane < 8) {
        int ee = warp * 4 + (lane >> 1);
        if (ee < E_real) v = __ldg(&ei[ee + ((lane & 1) ? E_real : 0)]);
    }
    int s = __shfl_sync(0xffffffffu, v, sub * 2);
    int d = __shfl_sync(0xffffffffu, v, sub * 2 + 1);

    float ex = 0.0f;
    if (act && sl < H1) {
        float val = lrelu(g_as1[s * H1 + sl] + g_ad1[d * H1 + sl]);
        ex = __expf(val);
        atomicAdd(&g_den1[d * H1 + sl], ex);
    }
    float exl = __shfl_sync(0xffffffffu, ex, sub * 8 + (sl >> 1));
    __half2 ex2 = __float2half2_rn(exl);

    const uint4* hp = (const uint4*)&g_h1h[s * F1 + sl * 16];
    uint4 r0 = __ldg(hp);
    uint4 r1 = __ldg(hp + 1);
    __half2 m0 = __hmul2(*(__half2*)&r0.x, ex2);
    __half2 m1 = __hmul2(*(__half2*)&r0.y, ex2);
    __half2 m2 = __hmul2(*(__half2*)&r0.z, ex2);
    __half2 m3 = __hmul2(*(__half2*)&r0.w, ex2);
    __half2 m4 = __hmul2(*(__half2*)&r1.x, ex2);
    __half2 m5 = __hmul2(*(__half2*)&r1.y, ex2);
    __half2 m6 = __hmul2(*(__half2*)&r1.z, ex2);
    __half2 m7 = __hmul2(*(__half2*)&r1.w, ex2);
    if (act) {
        __half* dst = &g_acc1h[d * F1 + sl * 16];
        asm volatile("red.global.add.noftz.v4.f16x2 [%0], {%1,%2,%3,%4};"
                     :: "l"(dst), "r"(*(unsigned*)&m0), "r"(*(unsigned*)&m1),
                        "r"(*(unsigned*)&m2), "r"(*(unsigned*)&m3) : "memory");
        asm volatile("red.global.add.noftz.v4.f16x2 [%0], {%1,%2,%3,%4};"
                     :: "l"(dst + 8), "r"(*(unsigned*)&m4), "r"(*(unsigned*)&m5),
                        "r"(*(unsigned*)&m6), "r"(*(unsigned*)&m7) : "memory");
    }
}

// ---------------- layer2 node: dequant+elu -> mma @W2 -> att2 + self-loop init ----------------
__global__ void l2gemm_kernel(const float* __restrict__ b1,
                              const float* __restrict__ att_s2,
                              const float* __restrict__ att_d2) {
    __shared__ __half hs[64 * XS];
    __shared__ __half w2s[OP * WS];
    __shared__ float es[64 * 20];
    __shared__ float b1s[F1];
    __shared__ float satt[2 * OUTC];

    int t = threadIdx.x;
    int row0 = blockIdx.x * 64;

    const uint4* wsrc = (const uint4*)g_W2h;
    for (int i = t; i < OP * F1 / 8; i += 256) {
        int n = i >> 4, kc = (i & 15) * 8;
        *(uint4*)&w2s[n * WS + kc] = wsrc[i];
    }
    if (t < F1) b1s[t] = b1[t];
    if (t >= 128 && t < 128 + OUTC) satt[t - 128] = att_s2[t - 128];
    if (t >= 160 && t < 160 + OUTC) satt[OUTC + t - 160] = att_d2[t - 160];
    __syncthreads();

#pragma unroll
    for (int j = 0; j < 4; j++) {
        int chunk = j * 256 + t;
        int r = chunk >> 4, part = chunk & 15;
        int ch0 = part * 8;
        int gr = row0 + r;
        uint4 raw = make_uint4(0, 0, 0, 0);
        float inv = 0.0f;
        if (gr < NN) {
            raw = *(const uint4*)&g_acc1h[gr * F1 + ch0];
            inv = 1.0f / (g_den1[gr * H1 + (part >> 2)] + 1e-16f);
        }
        const unsigned* rw = (const unsigned*)&raw;
        __half2 outp[4];
#pragma unroll
        for (int q = 0; q < 4; q++) {
            float2 f = __half22float2(*(__half2*)&rw[q]);
            float h0 = elu_fast(f.x * inv + b1s[ch0 + q * 2]);
            float h1 = elu_fast(f.y * inv + b1s[ch0 + q * 2 + 1]);
            outp[q] = __floats2half2_rn(h0, h1);
        }
        *(uint4*)&hs[r * XS + ch0] = *(uint4*)outp;
    }
    __syncthreads();

    int wid = t >> 5, lane = t & 31;
    int wm = wid & 3, wn = wid >> 2;
    int rq = lane >> 2;
    int q2 = (lane & 3) * 2;
    int rA = wm * 16 + rq;

    float c[4] = {0, 0, 0, 0};
#pragma unroll
    for (int kb = 0; kb < F1; kb += 16) {
        unsigned a0 = *(unsigned*)&hs[rA * XS + kb + q2];
        unsigned a1 = *(unsigned*)&hs[(rA + 8) * XS + kb + q2];
        unsigned a2 = *(unsigned*)&hs[rA * XS + kb + q2 + 8];
        unsigned a3 = *(unsigned*)&hs[(rA + 8) * XS + kb + q2 + 8];
        int n = wn * 8 + rq;
        unsigned b0 = *(unsigned*)&w2s[n * WS + kb + q2];
        unsigned b1r = *(unsigned*)&w2s[n * WS + kb + q2 + 8];
        mma16816(c, a0, a1, a2, a3, b0, b1r);
    }
    {
        int col = wn * 8 + q2;
        es[rA * 20 + col]           = c[0];
        es[rA * 20 + col + 1]       = c[1];
        es[(rA + 8) * 20 + col]     = c[2];
        es[(rA + 8) * 20 + col + 1] = c[3];
    }
    __syncthreads();

    if (t < 64) {
        int gr = row0 + t;
        if (gr < NN) {
            float as = 0.0f, ad = 0.0f;
            __half2 pk[8];
#pragma unroll
            for (int c2 = 0; c2 < 8; c2++) {
                float lo = (2 * c2 < OUTC)     ? es[t * 20 + 2 * c2]     : 0.0f;
                float hi = (2 * c2 + 1 < OUTC) ? es[t * 20 + 2 * c2 + 1] : 0.0f;
                pk[c2] = __floats2half2_rn(lo, hi);
                if (2 * c2 < OUTC)     { as += lo * satt[2 * c2];     ad += lo * satt[OUTC + 2 * c2]; }
                if (2 * c2 + 1 < OUTC) { as += hi * satt[2 * c2 + 1]; ad += hi * satt[OUTC + 2 * c2 + 1]; }
            }
            *(uint4*)&g_h2ph[gr * OP]     = *(uint4*)&pk[0];
            *(uint4*)&g_h2ph[gr * OP + 8] = *(uint4*)&pk[4];
            g_as2[gr] = as;
            g_ad2[gr] = ad;
            float ex = __expf(lrelu(as + ad));
            g_den2[gr] = ex;
            __half2 ex2 = __float2half2_rn(ex);
            __half2 ak[8];
#pragma unroll
            for (int c2 = 0; c2 < 8; c2++) ak[c2] = __hmul2(pk[c2], ex2);
            *(uint4*)&g_acc2ph[gr * OP]     = *(uint4*)&ak[0];
            *(uint4*)&g_acc2ph[gr * OP + 8] = *(uint4*)&ak[4];
        }
    }
}

// ---------------- edge accumulate layer2: 2 lanes per edge ----------------
__global__ void edge_acc2_kernel(const int* __restrict__ ei, int E_real) {
    int warp = (blockIdx.x * blockDim.x + threadIdx.x) >> 5;
    int lane = threadIdx.x & 31;
    int li = lane & 1;
    int ee = warp * 16 + (lane >> 1);
    bool act = (ee < E_real);

    int v = 0;
    if (act) v = __ldg(&ei[ee + (li ? E_real : 0)]);
    int s = __shfl_sync(0xffffffffu, v, lane & ~1);
    int d = __shfl_sync(0xffffffffu, v, lane | 1);

    float ex = 0.0f;
    if (act && li == 0) {
        ex = __expf(lrelu(g_as2[s] + g_ad2[d]));
        atomicAdd(&g_den2[d], ex);
    }
    ex = __shfl_sync(0xffffffffu, ex, lane & ~1);
    __half2 ex2 = __float2half2_rn(ex);
    uint4 raw = __ldg((const uint4*)&g_h2ph[s * OP + li * 8]);
    __half2 m0 = __hmul2(*(__half2*)&raw.x, ex2);
    __half2 m1 = __hmul2(*(__half2*)&raw.y, ex2);
    __half2 m2 = __hmul2(*(__half2*)&raw.z, ex2);
    __half2 m3 = __hmul2(*(__half2*)&raw.w, ex2);
    if (act) {
        __half* dst = &g_acc2ph[d * OP + li * 8];
        asm volatile("red.global.add.noftz.v4.f16x2 [%0], {%1,%2,%3,%4};"
                     :: "l"(dst), "r"(*(unsigned*)&m0), "r"(*(unsigned*)&m1),
                        "r"(*(unsigned*)&m2), "r"(*(unsigned*)&m3) : "memory");
    }
}

// ---------------- finalize layer2 + pooling (warp-aggregated atomics) ----------------
__global__ void fin2pool_kernel(const float* __restrict__ b2, const int* __restrict__ batch) {
    int n = blockIdx.x * blockDim.x + threadIdx.x;
    if (n >= NN) return;          // NN % 32 == 0 -> whole warps return together
    int lane = threadIdx.x & 31;
    float inv = 1.0f / (g_den2[n] + 1e-16f);
    int g = batch[n];
    float v[OUTC];
#pragma unroll
    for (int c = 0; c < OUTC; c++)
        v[c] = elu_fast(__half2float(g_acc2ph[n * OP + c]) * inv + b2[c]);

    int g0 = __shfl_sync(0xffffffffu, g, 0);
    bool uniform = __all_sync(0xffffffffu, g == g0);
    if (uniform) {
#pragma unroll
        for (int o = 16; o; o >>= 1)
#pragma unroll
            for (int c = 0; c < OUTC; c++)
                v[c] += __shfl_xor_sync(0xffffffffu, v[c], o);
        if (lane == 0) {
#pragma unroll
            for (int c = 0; c < OUTC; c++)
                atomicAdd(&g_pool[g0 * OUTC + c], v[c]);
            atomicAdd(&g_cnt[g0], 32.0f);
        }
    } else {
#pragma unroll
        for (int c = 0; c < OUTC; c++)
            atomicAdd(&g_pool[g * OUTC + c], v[c]);
        atomicAdd(&g_cnt[g], 1.0f);
    }
}

// ---------------- final: mean + log_softmax ----------------
__global__ void final_kernel(float* __restrict__ out) {
    int g = threadIdx.x;
    if (g >= NG) return;
    float cnt = fmaxf(g_cnt[g], 1.0f);
    float p[OUTC];
    float mx = -CUDART_INF_F;
#pragma unroll
    for (int c = 0; c < OUTC; c++) {
        p[c] = g_pool[g * OUTC + c] / cnt;
        mx = fmaxf(mx, p[c]);
    }
    float se = 0.0f;
#pragma unroll
    for (int c = 0; c < OUTC; c++) se += __expf(p[c] - mx);
    float lse = mx + __logf(se);
#pragma unroll
    for (int c = 0; c < OUTC; c++) out[g * OUTC + c] = p[c] - lse;
}

// ---------------- launch ----------------
extern "C" void kernel_launch(void* const* d_in, const int* in_sizes, int n_in,
                              void* d_out, int out_size) {
    const float* x      = (const float*)d_in[0];
    const float* W1     = (const float*)d_in[1];
    const float* att_s1 = (const float*)d_in[2];
    const float* att_d1 = (const float*)d_in[3];
    const float* b1     = (const float*)d_in[4];
    const float* W2     = (const float*)d_in[5];
    const float* att_s2 = (const float*)d_in[6];
    const float* att_d2 = (const float*)d_in[7];
    const float* b2     = (const float*)d_in[8];
    const int*   ei     = (const int*)d_in[9];
    const int*   batch  = (const int*)d_in[10];
    float* out = (float*)d_out;

    int E_real = in_sizes[9] / 2;

    void *p_pool, *p_cnt;
    cudaGetSymbolAddress(&p_pool, g_pool);
    cudaGetSymbolAddress(&p_cnt,  g_cnt);
    cudaMemsetAsync(p_pool, 0, (size_t)NG * OUTC * sizeof(float));
    cudaMemsetAsync(p_cnt,  0, (size_t)NG * sizeof(float));

    convert_w_kernel<<<(F1 * F1 + OP * F1 + 255) / 256, 256>>>(W1, W2);

    int gemm_smem = (F1 * WS + 64 * XS) * (int)sizeof(__half) + 512 * (int)sizeof(float);
    cudaFuncSetAttribute(gemm1_att_kernel, cudaFuncAttributeMaxDynamicSharedMemorySize, gemm_smem);
    gemm1_att_kernel<<<(NN + 63) / 64, 256, gemm_smem>>>(x, att_s1, att_d1);

    long long w1 = ((long long)E_real + 3) / 4;
    edge_acc1_kernel<<<(int)((w1 * 32 + 255) / 256), 256>>>(ei, E_real);

    l2gemm_kernel<<<(NN + 63) / 64, 256>>>(b1, att_s2, att_d2);

    long long w2 = ((long long)E_real + 15) / 16;
    edge_acc2_kernel<<<(int)((w2 * 32 + 255) / 256), 256>>>(ei, E_real);

    fin2pool_kernel<<<(NN + 255) / 256, 256>>>(b2, batch);

    final_kernel<<<1, NG>>>(out);
}